// round 9
// baseline (speedup 1.0000x reference)
#include <cuda_runtime.h>
#include <math.h>

// Problem constants
#define Bsz 8
#define Cch 512
#define Hh 64
#define Ww 64
#define Ls 4096
#define Gg 4
#define Dd 128
#define Mrows 32768   // B*L

// ---------------- scratch (device globals; no cudaMalloc allowed) -------------
__device__ float g_xn  [(size_t)Bsz*Ls*Cch];        // [b][l][c]  LN1 output
__device__ float g_zp  [32*Bsz*Cch];                // partial sums for z-mean
__device__ float g_gate[Bsz*Cch];
__device__ float g_xz  [(size_t)Gg*Mrows*256];      // [g][m][e]: e<128 raw xd, e>=128 silu(z)
__device__ float g_u   [(size_t)Gg*Mrows*Dd];       // scan-order u
__device__ float g_dA  [(size_t)Gg*Mrows*Dd];
__device__ float g_dbu [(size_t)Gg*Mrows*Dd];
__device__ float g_Cv  [Gg*Mrows];
__device__ float g_P   [Gg*Bsz*64*Dd];
__device__ float g_hc  [Gg*Bsz*64*Dd];
__device__ float g_hin [Gg*Bsz*64*Dd];
__device__ float g_y   [(size_t)Gg*Mrows*Dd];       // scan output (scan order)
__device__ float g_yz  [(size_t)Gg*Mrows*Dd];       // merged LN*z (spatial order)
__device__ float g_ycat[(size_t)Mrows*Cch];
__device__ float g_xmn [(size_t)Mrows*Cch];

// ---------------- kernel 1: layernorm over C (+ write [b][l][c]) --------------
__global__ void k_ln1(const float* __restrict__ x,
                      const float* __restrict__ lg, const float* __restrict__ lb)
{
    int b = blockIdx.y;
    int l = blockIdx.x * 128 + threadIdx.x;
    const float* xp = x + (size_t)b * Cch * Ls + l;
    float s = 0.f, s2 = 0.f;
#pragma unroll 8
    for (int c = 0; c < Cch; c++) { float v = xp[(size_t)c * Ls]; s += v; s2 += v * v; }
    float mu = s * (1.f / Cch);
    float rs = rsqrtf(s2 * (1.f / Cch) - mu * mu + 1e-5f);
    float* out = g_xn + ((size_t)b * Ls + l) * Cch;
#pragma unroll 4
    for (int c = 0; c < Cch; c += 4) {
        float4 o;
        o.x = (xp[(size_t)(c + 0) * Ls] - mu) * rs * lg[c + 0] + lb[c + 0];
        o.y = (xp[(size_t)(c + 1) * Ls] - mu) * rs * lg[c + 1] + lb[c + 1];
        o.z = (xp[(size_t)(c + 2) * Ls] - mu) * rs * lg[c + 2] + lb[c + 2];
        o.w = (xp[(size_t)(c + 3) * Ls] - mu) * rs * lg[c + 3] + lb[c + 3];
        *(float4*)(out + c) = o;
    }
}

// ---------------- kernel 2: partial column sums of xn (for z mean) ------------
__global__ void k_zsum()
{
    int b = blockIdx.y, k = blockIdx.x, c = threadIdx.x;
    const float* p = g_xn + ((size_t)b * Ls + k * 128) * Cch + c;
    float s = 0.f;
#pragma unroll 8
    for (int i = 0; i < 128; i++) s += p[(size_t)i * Cch];
    g_zp[(k * Bsz + b) * Cch + c] = s;
}

// ---------------- kernel 3: gate MLP (tiny, single block) ---------------------
__global__ void k_gate(const float* __restrict__ fc1w, const float* __restrict__ fc1b,
                       const float* __restrict__ fc2w, const float* __restrict__ fc2b)
{
    __shared__ float zsm[Bsz * Cch];
    __shared__ float hsm[Bsz * 32];
    int t = threadIdx.x;
    for (int idx = t; idx < Bsz * Cch; idx += 256) {
        int b = idx >> 9, c = idx & 511;
        float s = 0.f;
        for (int k = 0; k < 32; k++) s += g_zp[(k * Bsz + b) * Cch + c];
        zsm[idx] = s * (1.f / Ls);
    }
    __syncthreads();
    {   // hidden: 8 batches x 32
        int b = t >> 5, r = t & 31;
        float s = fc1b[r];
        for (int c = 0; c < Cch; c++) s += zsm[b * Cch + c] * fc1w[r * Cch + c];
        hsm[t] = fmaxf(s, 0.f);
    }
    __syncthreads();
    for (int idx = t; idx < Bsz * Cch; idx += 256) {
        int b = idx >> 9, c = idx & 511;
        float s = fc2b[c];
#pragma unroll
        for (int r = 0; r < 32; r++) s += hsm[b * 32 + r] * fc2w[c * 32 + r];
        g_gate[idx] = 1.f / (1.f + expf(-s));
    }
}

// ---------------- shared SIMT GEMM core (BM=BN=128, BK=16, 256 thr, 8x8) ------
__device__ __forceinline__ void gemm_tile(const float* __restrict__ A, int lda,
                                          const float* __restrict__ Bw, int K,
                                          int mBase, int nBase,
                                          float acc[8][8], float* As, float* Bs)
{
    int tid = threadIdx.x;
    for (int k0 = 0; k0 < K; k0 += 16) {
#pragma unroll
        for (int i = 0; i < 2; i++) {
            int tt = tid + i * 256;
            int row = tt >> 2, kq = (tt & 3) * 4;
            float4 v = *(const float4*)(A + (size_t)(mBase + row) * lda + k0 + kq);
            As[(kq + 0) * 128 + row] = v.x; As[(kq + 1) * 128 + row] = v.y;
            As[(kq + 2) * 128 + row] = v.z; As[(kq + 3) * 128 + row] = v.w;
            float4 w = *(const float4*)(Bw + (size_t)(nBase + row) * K + k0 + kq);
            Bs[(kq + 0) * 128 + row] = w.x; Bs[(kq + 1) * 128 + row] = w.y;
            Bs[(kq + 2) * 128 + row] = w.z; Bs[(kq + 3) * 128 + row] = w.w;
        }
        __syncthreads();
        int tm = (tid & 15) * 8, tn = (tid >> 4) * 8;
#pragma unroll
        for (int k = 0; k < 16; k++) {
            float a[8], bb[8];
            *(float4*)(a)      = *(float4*)(As + k * 128 + tm);
            *(float4*)(a + 4)  = *(float4*)(As + k * 128 + tm + 4);
            *(float4*)(bb)     = *(float4*)(Bs + k * 128 + tn);
            *(float4*)(bb + 4) = *(float4*)(Bs + k * 128 + tn + 4);
#pragma unroll
            for (int i = 0; i < 8; i++)
#pragma unroll
                for (int j = 0; j < 8; j++) acc[i][j] += a[i] * bb[j];
        }
        __syncthreads();
    }
}

// ---------------- kernel 4: in_proj GEMM (batched over g) ---------------------
__global__ void __launch_bounds__(256) k_gemm_in(const float* __restrict__ ipw)
{
    __shared__ float As[16 * 128], Bs[16 * 128];
    int g = blockIdx.z;
    int mBase = blockIdx.x * 128, nBase = blockIdx.y * 128;
    float acc[8][8] = {};
    gemm_tile(g_xn + g * 128, Cch, ipw + (size_t)g * 256 * 128, 128, mBase, nBase, acc, As, Bs);
    int tid = threadIdx.x, tm = (tid & 15) * 8, tn = (tid >> 4) * 8;
    bool dosilu = (nBase >= 128);
    float* Cp = g_xz + (size_t)g * Mrows * 256;
#pragma unroll
    for (int i = 0; i < 8; i++) {
        float vals[8];
#pragma unroll
        for (int j = 0; j < 8; j++) {
            float v = acc[i][j];
            if (dosilu) v = v / (1.f + expf(-v));
            vals[j] = v;
        }
        float* op = Cp + (size_t)(mBase + tm + i) * 256 + nBase + tn;
        *(float4*)op = *(float4*)vals; *(float4*)(op + 4) = *(float4*)(vals + 4);
    }
}

// ---------------- kernel 5: depthwise 3x3 conv + silu + cross_scan write ------
__global__ void __launch_bounds__(256) k_conv(const float* __restrict__ cw,
                                              const float* __restrict__ cb)
{
    __shared__ float sx[324 * 32];
    __shared__ float wsm[32 * 9];
    __shared__ float bsm[32];
    int tile = blockIdx.x, dt = blockIdx.y, gb = blockIdx.z;
    int g = gb >> 3, b = gb & 7;
    int h0 = (tile >> 2) * 16, w0 = (tile & 3) * 16;
    int dbase = dt * 32;
    int tid = threadIdx.x;
    const float* src = g_xz + ((size_t)g * Mrows + b * Ls) * 256;
    for (int idx = tid; idx < 324 * 32; idx += 256) {
        int pos = idx >> 5, dd = idx & 31;
        int h = h0 + pos / 18 - 1, w = w0 + pos % 18 - 1;
        float v = 0.f;
        if (h >= 0 && h < 64 && w >= 0 && w < 64)
            v = src[(size_t)(h * 64 + w) * 256 + dbase + dd];
        sx[idx] = v;
    }
    // FIX: 288 weights > 256 threads — must stride, not guard
    for (int i = tid; i < 288; i += 256)
        wsm[i] = cw[(size_t)(g * 128 + dbase + i / 9) * 9 + i % 9];
    if (tid < 32)  bsm[tid] = cb[g * 128 + dbase + tid];
    __syncthreads();
    int dd = tid & 31;
    float* dstbase = g_u + ((size_t)g * Mrows + b * Ls) * 128 + dbase + dd;
#pragma unroll 4
    for (int it = 0; it < 32; it++) {
        int pos = it * 8 + (tid >> 5);
        int ph = pos >> 4, pw = pos & 15;
        float acc = bsm[dd];
#pragma unroll
        for (int kh = 0; kh < 3; kh++)
#pragma unroll
            for (int kw = 0; kw < 3; kw++)
                acc += sx[((ph + kh) * 18 + pw + kw) * 32 + dd] * wsm[dd * 9 + kh * 3 + kw];
        acc = acc / (1.f + expf(-acc));
        int h = h0 + ph, w = w0 + pw;
        int lp;
        if (g == 0)      lp = h * 64 + w;
        else if (g == 1) lp = w * 64 + h;
        else if (g == 2) lp = 4095 - (h * 64 + w);
        else             lp = 4095 - (w * 64 + h);
        dstbase[(size_t)lp * 128] = acc;
    }
}

// ---------------- kernel 6: x_proj + dt_proj + dA/dBu/C -----------------------
__global__ void __launch_bounds__(256) k_proj(const float* __restrict__ xpw,
                                              const float* __restrict__ dtw_g,
                                              const float* __restrict__ dtb_g,
                                              const float* __restrict__ alog)
{
    __shared__ float xp[10 * 128];
    __shared__ float dtwT[8 * 128];
    __shared__ float dtb[128];
    __shared__ float An[128];
    int tid = threadIdx.x, lane = tid & 31, warp = tid >> 5;
    int chunk0 = blockIdx.x * 8;
    int g = chunk0 >> 12;
    for (int i = tid; i < 1280; i += 256) xp[i] = xpw[(size_t)g * 1280 + i];
    for (int i = tid; i < 1024; i += 256) {
        int r = i >> 7, d = i & 127;
        dtwT[i] = dtw_g[(size_t)(g * 128 + d) * 8 + r];
    }
    if (tid < 128) { dtb[tid] = dtb_g[g * 128 + tid]; An[tid] = -expf(alog[g * 128 + tid]); }
    __syncthreads();
    int chunk = chunk0 + warp;
    int b = (chunk >> 9) & 7;
    int lp0 = (chunk & 511) * 8;
    size_t rowbase = (size_t)(g * 8 + b) * 4096 + lp0;
    for (int it = 0; it < 8; it++) {
        size_t row = rowbase + it;
        float4 u4 = *(const float4*)(g_u + row * 128 + lane * 4);
        float xdbl[10];
#pragma unroll
        for (int c = 0; c < 10; c++) {
            const float* xc = xp + c * 128 + lane * 4;
            float p = u4.x * xc[0] + u4.y * xc[1] + u4.z * xc[2] + u4.w * xc[3];
#pragma unroll
            for (int o = 16; o; o >>= 1) p += __shfl_xor_sync(0xffffffffu, p, o);
            xdbl[c] = p;
        }
        float Bm = xdbl[8];
        float uarr[4] = { u4.x, u4.y, u4.z, u4.w };
        float dA4[4], db4[4];
#pragma unroll
        for (int j = 0; j < 4; j++) {
            int d = lane * 4 + j;
            float s = dtb[d];
#pragma unroll
            for (int r = 0; r < 8; r++) s += xdbl[r] * dtwT[r * 128 + d];
            float delta = (s > 20.f) ? s : log1pf(expf(s));
            dA4[j] = expf(delta * An[d]);
            db4[j] = delta * uarr[j] * Bm;
        }
        *(float4*)(g_dA  + row * 128 + lane * 4) = *(float4*)dA4;
        *(float4*)(g_dbu + row * 128 + lane * 4) = *(float4*)db4;
        if (lane == 0) g_Cv[row] = xdbl[9];
    }
}

// ---------------- kernels 7-9: chunked parallel linear scan --------------------
__global__ void k_scanA()
{
    int chunk = blockIdx.x, gb = blockIdx.y, d = threadIdx.x;
    size_t base = ((size_t)gb * 4096 + chunk * 64) * 128 + d;
    float h = 0.f, P = 1.f;
#pragma unroll 4
    for (int i = 0; i < 64; i++) {
        float a = g_dA[base + (size_t)i * 128], bu = g_dbu[base + (size_t)i * 128];
        h = fmaf(a, h, bu); P *= a;
    }
    size_t o = ((size_t)gb * 64 + chunk) * 128 + d;
    g_P[o] = P; g_hc[o] = h;
}

__global__ void k_scanB()
{
    int gb = blockIdx.x, d = threadIdx.x;
    float h = 0.f;
    for (int ch = 0; ch < 64; ch++) {
        size_t o = ((size_t)gb * 64 + ch) * 128 + d;
        g_hin[o] = h;
        h = fmaf(g_P[o], h, g_hc[o]);
    }
}

__global__ void k_scanC(const float* __restrict__ Dsp)
{
    int chunk = blockIdx.x, gb = blockIdx.y, d = threadIdx.x;
    int g = gb >> 3;
    float Ds = Dsp[g * 128 + d];
    size_t base = ((size_t)gb * 4096 + chunk * 64) * 128 + d;
    size_t crow = (size_t)gb * 4096 + chunk * 64;
    float h = g_hin[((size_t)gb * 64 + chunk) * 128 + d];
#pragma unroll 4
    for (int i = 0; i < 64; i++) {
        size_t idx = base + (size_t)i * 128;
        h = fmaf(g_dA[idx], h, g_dbu[idx]);
        g_y[idx] = h * g_Cv[crow + i] + Ds * g_u[idx];
    }
}

// ---------------- kernel 10: cross_merge + LN(D) + *z --------------------------
__global__ void __launch_bounds__(256) k_merge(const float* __restrict__ og_,
                                               const float* __restrict__ ob_)
{
    __shared__ float og[128], ob[128];
    int tid = threadIdx.x, lane = tid & 31, warp = tid >> 5;
    int chunk0 = blockIdx.x * 8;
    int g = chunk0 >> 12;
    if (tid < 128) { og[tid] = og_[g * 128 + tid]; ob[tid] = ob_[g * 128 + tid]; }
    __syncthreads();
    int chunk = chunk0 + warp;
    int b = (chunk >> 9) & 7;
    int l0 = (chunk & 511) * 8;
    for (int it = 0; it < 8; it++) {
        int l = l0 + it;
        int h = l >> 6, w = l & 63;
        int lp;
        if (g == 0)      lp = l;
        else if (g == 1) lp = w * 64 + h;
        else if (g == 2) lp = 4095 - l;
        else             lp = 4095 - (w * 64 + h);
        size_t srow = (size_t)(g * 8 + b) * 4096 + lp;
        float4 y4 = *(const float4*)(g_y + srow * 128 + lane * 4);
        float s  = y4.x + y4.y + y4.z + y4.w;
        float s2 = y4.x * y4.x + y4.y * y4.y + y4.z * y4.z + y4.w * y4.w;
#pragma unroll
        for (int o = 16; o; o >>= 1) {
            s  += __shfl_xor_sync(0xffffffffu, s, o);
            s2 += __shfl_xor_sync(0xffffffffu, s2, o);
        }
        float mu = s * (1.f / 128.f);
        float rs = rsqrtf(s2 * (1.f / 128.f) - mu * mu + 1e-5f);
        size_t drow = (size_t)(g * 8 + b) * 4096 + l;
        float4 z4 = *(const float4*)(g_xz + drow * 256 + 128 + lane * 4);
        float yv[4] = { y4.x, y4.y, y4.z, y4.w };
        float zv[4] = { z4.x, z4.y, z4.z, z4.w };
        float outv[4];
#pragma unroll
        for (int j = 0; j < 4; j++) {
            int d = lane * 4 + j;
            outv[j] = ((yv[j] - mu) * rs * og[d] + ob[d]) * zv[j];
        }
        *(float4*)(g_yz + drow * 128 + lane * 4) = *(float4*)outv;
    }
}

// ---------------- kernel 11: out_proj GEMM (batched over g) --------------------
__global__ void __launch_bounds__(256) k_gemm_out(const float* __restrict__ opw)
{
    __shared__ float As[16 * 128], Bs[16 * 128];
    int g = blockIdx.z;
    int mBase = blockIdx.x * 128;
    float acc[8][8] = {};
    gemm_tile(g_yz + (size_t)g * Mrows * 128, 128, opw + (size_t)g * 128 * 128, 128,
              mBase, 0, acc, As, Bs);
    int tid = threadIdx.x, tm = (tid & 15) * 8, tn = (tid >> 4) * 8;
#pragma unroll
    for (int i = 0; i < 8; i++) {
        float* op = g_ycat + (size_t)(mBase + tm + i) * 512 + g * 128 + tn;
        *(float4*)op = *(float4*)&acc[i][0]; *(float4*)(op + 4) = *(float4*)&acc[i][4];
    }
}

// ---------------- kernel 12: mix + gate + LN(C) --------------------------------
__global__ void __launch_bounds__(128) k_premix(const float* __restrict__ lg,
                                                const float* __restrict__ lb,
                                                const float* __restrict__ skip)
{
    int row = blockIdx.x, b = row >> 12, tid = threadIdx.x;
    float sk = skip[0];
    float4 yc = *(const float4*)(g_ycat + (size_t)row * 512 + tid * 4);
    float4 xn = *(const float4*)(g_xn   + (size_t)row * 512 + tid * 4);
    float4 gt = *(const float4*)(g_gate + (size_t)b   * 512 + tid * 4);
    float v[4] = { yc.x * sk * xn.x * gt.x, yc.y * sk * xn.y * gt.y,
                   yc.z * sk * xn.z * gt.z, yc.w * sk * xn.w * gt.w };
    float s  = v[0] + v[1] + v[2] + v[3];
    float s2 = v[0] * v[0] + v[1] * v[1] + v[2] * v[2] + v[3] * v[3];
#pragma unroll
    for (int o = 16; o; o >>= 1) {
        s  += __shfl_xor_sync(0xffffffffu, s, o);
        s2 += __shfl_xor_sync(0xffffffffu, s2, o);
    }
    __shared__ float rs_[4], rq_[4];
    int warp = tid >> 5, lane = tid & 31;
    if (lane == 0) { rs_[warp] = s; rq_[warp] = s2; }
    __syncthreads();
    s  = rs_[0] + rs_[1] + rs_[2] + rs_[3];
    s2 = rq_[0] + rq_[1] + rq_[2] + rq_[3];
    float mu = s * (1.f / 512.f);
    float rstd = rsqrtf(s2 * (1.f / 512.f) - mu * mu + 1e-5f);
    float o4[4];
#pragma unroll
    for (int j = 0; j < 4; j++) {
        int c = tid * 4 + j;
        o4[j] = (v[j] - mu) * rstd * lg[c] + lb[c];
    }
    *(float4*)(g_xmn + (size_t)row * 512 + tid * 4) = *(float4*)o4;
}

// ---------------- kernel 13: final proj GEMM (output transposed) ---------------
__global__ void __launch_bounds__(256) k_gemm_fin(const float* __restrict__ pw,
                                                  const float* __restrict__ pb,
                                                  float* __restrict__ out)
{
    __shared__ float As[16 * 128], Bs[16 * 128];
    int mBase = blockIdx.x * 128, nBase = blockIdx.y * 128;
    float acc[8][8] = {};
    gemm_tile(g_xmn, 512, pw, 512, mBase, nBase, acc, As, Bs);
    int tid = threadIdx.x, tm = (tid & 15) * 8, tn = (tid >> 4) * 8;
    int m0 = mBase + tm;
    int b = m0 >> 12, l = m0 & 4095;
#pragma unroll
    for (int j = 0; j < 8; j++) {
        int n = nBase + tn + j;
        float bias = __ldg(pb + n);
        float a0[4] = { acc[0][j] + bias, acc[1][j] + bias, acc[2][j] + bias, acc[3][j] + bias };
        float a1[4] = { acc[4][j] + bias, acc[5][j] + bias, acc[6][j] + bias, acc[7][j] + bias };
        float* op = out + ((size_t)(b * 512 + n)) * 4096 + l;
        *(float4*)op = *(float4*)a0; *(float4*)(op + 4) = *(float4*)a1;
    }
}

// ---------------- launch ---------------------------------------------------------
extern "C" void kernel_launch(void* const* d_in, const int* in_sizes, int n_in,
                              void* d_out, int out_size)
{
    const float* x    = (const float*)d_in[0];
    const float* ln_g = (const float*)d_in[1];
    const float* ln_b = (const float*)d_in[2];
    const float* fc1w = (const float*)d_in[3];
    const float* fc1b = (const float*)d_in[4];
    const float* fc2w = (const float*)d_in[5];
    const float* fc2b = (const float*)d_in[6];
    const float* ipw  = (const float*)d_in[7];
    const float* cw   = (const float*)d_in[8];
    const float* cb   = (const float*)d_in[9];
    const float* xpw  = (const float*)d_in[10];
    const float* dtw  = (const float*)d_in[11];
    const float* dtb  = (const float*)d_in[12];
    const float* alog = (const float*)d_in[13];
    const float* dsp  = (const float*)d_in[14];
    const float* ong  = (const float*)d_in[15];
    const float* onb  = (const float*)d_in[16];
    const float* opw  = (const float*)d_in[17];
    const float* pw   = (const float*)d_in[18];
    const float* pb   = (const float*)d_in[19];
    const float* skip = (const float*)d_in[20];
    float* out = (float*)d_out;

    k_ln1      <<<dim3(32, 8),     128>>>(x, ln_g, ln_b);
    k_zsum     <<<dim3(32, 8),     512>>>();
    k_gate     <<<1,               256>>>(fc1w, fc1b, fc2w, fc2b);
    k_gemm_in  <<<dim3(256, 2, 4), 256>>>(ipw);
    k_conv     <<<dim3(16, 4, 32), 256>>>(cw, cb);
    k_proj     <<<2048,            256>>>(xpw, dtw, dtb, alog);
    k_scanA    <<<dim3(64, 32),    128>>>();
    k_scanB    <<<32,              128>>>();
    k_scanC    <<<dim3(64, 32),    128>>>(dsp);
    k_merge    <<<2048,            256>>>(ong, onb);
    k_gemm_out <<<dim3(256, 1, 4), 256>>>(opw);
    k_premix   <<<32768,           128>>>(ln_g, ln_b, skip);
    k_gemm_fin <<<dim3(256, 4),    256>>>(pw, pb, out);
}

// round 11
// speedup vs baseline: 1.5884x; 1.5884x over previous
#include <cuda_runtime.h>
#include <math.h>
#include <stdint.h>

// Problem constants
#define Bsz 8
#define Cch 512
#define Ls 4096
#define Gg 4
#define Dd 128
#define Mrows 32768   // B*L

// ---------------- scratch (device globals; no cudaMalloc allowed) -------------
__device__ float g_xn  [(size_t)Bsz*Ls*Cch];
__device__ float g_zp  [32*Bsz*Cch];
__device__ float g_gate[Bsz*Cch];
__device__ float g_xz  [(size_t)Gg*Mrows*256];
__device__ float g_u   [(size_t)Gg*Mrows*Dd];
__device__ float g_dA  [(size_t)Gg*Mrows*Dd];
__device__ float g_dbu [(size_t)Gg*Mrows*Dd];
__device__ float g_Cv  [Gg*Mrows];
__device__ float g_P   [Gg*Bsz*64*Dd];
__device__ float g_hc  [Gg*Bsz*64*Dd];
__device__ float g_hin [Gg*Bsz*64*Dd];
__device__ float g_y   [(size_t)Gg*Mrows*Dd];
__device__ float g_yz  [(size_t)Gg*Mrows*Dd];
__device__ float g_ycat[(size_t)Mrows*Cch];
__device__ float g_xmn [(size_t)Mrows*Cch];
// tf32-rounded weight copies
__device__ float g_ipw [Gg*256*128];
__device__ float g_opw [Gg*128*128];
__device__ float g_pw  [512*512];

// ---------------- helpers -------------------------------------------------------
__device__ __forceinline__ float tf32r(float x) {
    uint32_t u;
    asm("cvt.rna.tf32.f32 %0, %1;" : "=r"(u) : "f"(x));
    return __uint_as_float(u);
}
__device__ __forceinline__ uint32_t sm_u32(const void* p) {
    return (uint32_t)__cvta_generic_to_shared(p);
}
__device__ __forceinline__ void cpa16(uint32_t dst, const float* src) {
    asm volatile("cp.async.cg.shared.global [%0], [%1], 16;" :: "r"(dst), "l"(src));
}
__device__ __forceinline__ void cpa_commit() { asm volatile("cp.async.commit_group;"); }
template<int N> __device__ __forceinline__ void cpa_wait() {
    asm volatile("cp.async.wait_group %0;" :: "n"(N));
}
__device__ __forceinline__ void mma_tf32_16n8k8(float* c, const uint32_t* a, const uint32_t* b) {
    asm volatile(
        "mma.sync.aligned.m16n8k8.row.col.f32.tf32.tf32.f32 "
        "{%0,%1,%2,%3}, {%4,%5,%6,%7}, {%8,%9}, {%0,%1,%2,%3};"
        : "+f"(c[0]), "+f"(c[1]), "+f"(c[2]), "+f"(c[3])
        : "r"(a[0]), "r"(a[1]), "r"(a[2]), "r"(a[3]), "r"(b[0]), "r"(b[1]));
}

// SMEM stage: 128 rows x 16 cols, row pitch 20 floats (conflict-free fragments)
#define SPITCH 20
#define STAGE_FLOATS (128 * SPITCH)

__device__ __forceinline__ void stage_load(const float* __restrict__ g, int ld,
                                           int r0, int k0, float* sbuf, int tid)
{
#pragma unroll
    for (int i = 0; i < 2; i++) {
        int s = tid + (i << 8);          // 0..511
        int r = s >> 2, seg = s & 3;
        cpa16(sm_u32(sbuf + r * SPITCH + seg * 4),
              g + (size_t)(r0 + r) * ld + k0 + seg * 4);
    }
}

// ---------------- tf32 mma.sync 128x128xK core ----------------------------------
// 256 threads = 8 warps, warp grid 4(M) x 2(N); warp tile 32x64.
// acc[mt][nt][4]: mt in 0..1 (16 rows each), nt in 0..7 (8 cols each).
template<int S>   // S = K/16 stages
__device__ __forceinline__ void mma_gemm(const float* __restrict__ Ag, int lda,
                                         const float* __restrict__ Bg,
                                         int mBase, int nBase,
                                         float acc[2][8][4],
                                         float* As, float* Bs)
{
    const int KTOT = 16 * S;
    int tid = threadIdx.x, wid = tid >> 5, lane = tid & 31;
    int gid = lane >> 2, tidx = lane & 3;
    int wm = (wid & 3) * 32, wn = (wid >> 2) * 64;

    stage_load(Ag, lda, mBase, 0, As, tid);
    stage_load(Bg, KTOT, nBase, 0, Bs, tid);
    cpa_commit();

    for (int s = 0; s < S; s++) {
        if (s + 1 < S) {
            int nb = (s + 1) & 1;
            stage_load(Ag, lda, mBase, (s + 1) * 16, As + nb * STAGE_FLOATS, tid);
            stage_load(Bg, KTOT, nBase, (s + 1) * 16, Bs + nb * STAGE_FLOATS, tid);
            cpa_commit();
            cpa_wait<1>();
        } else {
            cpa_wait<0>();
        }
        __syncthreads();
        const float* Ab = As + (s & 1) * STAGE_FLOATS;
        const float* Bb = Bs + (s & 1) * STAGE_FLOATS;
#pragma unroll
        for (int kk = 0; kk < 16; kk += 8) {
            uint32_t afr[2][4];
#pragma unroll
            for (int mt = 0; mt < 2; mt++) {
                const float* ap = Ab + (wm + mt * 16 + gid) * SPITCH + kk + tidx;
                afr[mt][0] = __float_as_uint(ap[0]);
                afr[mt][1] = __float_as_uint(ap[8 * SPITCH]);
                afr[mt][2] = __float_as_uint(ap[4]);
                afr[mt][3] = __float_as_uint(ap[8 * SPITCH + 4]);
            }
            uint32_t bfr[8][2];
#pragma unroll
            for (int nt = 0; nt < 8; nt++) {
                const float* bp = Bb + (wn + nt * 8 + gid) * SPITCH + kk + tidx;
                bfr[nt][0] = __float_as_uint(bp[0]);
                bfr[nt][1] = __float_as_uint(bp[4]);
            }
#pragma unroll
            for (int mt = 0; mt < 2; mt++)
#pragma unroll
                for (int nt = 0; nt < 8; nt++)
                    mma_tf32_16n8k8(acc[mt][nt], afr[mt], bfr[nt]);
        }
        __syncthreads();
    }
}

// ---------------- kernel 1: layernorm over C ----------------------------------
__global__ void k_ln1(const float* __restrict__ x,
                      const float* __restrict__ lg, const float* __restrict__ lb)
{
    int b = blockIdx.y;
    int l = blockIdx.x * 128 + threadIdx.x;
    const float* xp = x + (size_t)b * Cch * Ls + l;
    float s = 0.f, s2 = 0.f;
#pragma unroll 8
    for (int c = 0; c < Cch; c++) { float v = xp[(size_t)c * Ls]; s += v; s2 += v * v; }
    float mu = s * (1.f / Cch);
    float rs = rsqrtf(s2 * (1.f / Cch) - mu * mu + 1e-5f);
    float* out = g_xn + ((size_t)b * Ls + l) * Cch;
#pragma unroll 4
    for (int c = 0; c < Cch; c += 4) {
        float4 o;
        o.x = tf32r((xp[(size_t)(c + 0) * Ls] - mu) * rs * lg[c + 0] + lb[c + 0]);
        o.y = tf32r((xp[(size_t)(c + 1) * Ls] - mu) * rs * lg[c + 1] + lb[c + 1]);
        o.z = tf32r((xp[(size_t)(c + 2) * Ls] - mu) * rs * lg[c + 2] + lb[c + 2]);
        o.w = tf32r((xp[(size_t)(c + 3) * Ls] - mu) * rs * lg[c + 3] + lb[c + 3]);
        *(float4*)(out + c) = o;
    }
}

// ---------------- kernel 2: partial column sums -------------------------------
__global__ void k_zsum()
{
    int b = blockIdx.y, k = blockIdx.x, c = threadIdx.x;
    const float* p = g_xn + ((size_t)b * Ls + k * 128) * Cch + c;
    float s = 0.f;
#pragma unroll 8
    for (int i = 0; i < 128; i++) s += p[(size_t)i * Cch];
    g_zp[(k * Bsz + b) * Cch + c] = s;
}

// ---------------- kernel 3: gate MLP -------------------------------------------
__global__ void k_gate(const float* __restrict__ fc1w, const float* __restrict__ fc1b,
                       const float* __restrict__ fc2w, const float* __restrict__ fc2b)
{
    __shared__ float zsm[Bsz * Cch];
    __shared__ float hsm[Bsz * 32];
    int t = threadIdx.x;
    for (int idx = t; idx < Bsz * Cch; idx += 256) {
        int b = idx >> 9, c = idx & 511;
        float s = 0.f;
        for (int k = 0; k < 32; k++) s += g_zp[(k * Bsz + b) * Cch + c];
        zsm[idx] = s * (1.f / Ls);
    }
    __syncthreads();
    {
        int b = t >> 5, r = t & 31;
        float s = fc1b[r];
        for (int c = 0; c < Cch; c++) s += zsm[b * Cch + c] * fc1w[r * Cch + c];
        hsm[t] = fmaxf(s, 0.f);
    }
    __syncthreads();
    for (int idx = t; idx < Bsz * Cch; idx += 256) {
        int b = idx >> 9, c = idx & 511;
        float s = fc2b[c];
#pragma unroll
        for (int r = 0; r < 32; r++) s += hsm[b * 32 + r] * fc2w[c * 32 + r];
        g_gate[idx] = 1.f / (1.f + expf(-s));
    }
}

// ---------------- weight rounding (tf32 RNE) ------------------------------------
__global__ void k_roundw(const float* __restrict__ ipw, const float* __restrict__ opw,
                         const float* __restrict__ pw)
{
    int i = blockIdx.x * 256 + threadIdx.x;
    if (i < Gg * 256 * 128) g_ipw[i] = tf32r(ipw[i]);
    if (i < Gg * 128 * 128) g_opw[i] = tf32r(opw[i]);
    if (i < 512 * 512)      g_pw[i]  = tf32r(pw[i]);
}

// ---------------- GEMM 1: in_proj (fused SiLU on z half) ------------------------
__global__ void __launch_bounds__(256) k_gemm_in_mma()
{
    __shared__ float As[2 * STAGE_FLOATS], Bs[2 * STAGE_FLOATS];
    int g = blockIdx.z;
    int mBase = blockIdx.x * 128, nBase = blockIdx.y * 128;
    float acc[2][8][4] = {};
    mma_gemm<8>(g_xn + g * 128, Cch, g_ipw + (size_t)g * 256 * 128,
                mBase, nBase, acc, As, Bs);
    int lane = threadIdx.x & 31, wid = threadIdx.x >> 5;
    int gid = lane >> 2, tidx = lane & 3;
    int wm = (wid & 3) * 32, wn = (wid >> 2) * 64;
    bool dosilu = (nBase >= 128);
    float* Cp = g_xz + (size_t)g * Mrows * 256;
#pragma unroll
    for (int mt = 0; mt < 2; mt++)
#pragma unroll
    for (int half = 0; half < 2; half++) {
        int m = mBase + wm + mt * 16 + gid + half * 8;
        float* dst = Cp + (size_t)m * 256 + nBase + wn + 2 * tidx;
#pragma unroll
        for (int nt = 0; nt < 8; nt++) {
            float v0 = acc[mt][nt][half * 2], v1 = acc[mt][nt][half * 2 + 1];
            if (dosilu) { v0 = v0 / (1.f + expf(-v0)); v1 = v1 / (1.f + expf(-v1)); }
            float2 o = { v0, v1 };
            *(float2*)(dst + nt * 8) = o;
        }
    }
}

// ---------------- GEMM 2: out_proj ----------------------------------------------
__global__ void __launch_bounds__(256) k_gemm_out_mma()
{
    __shared__ float As[2 * STAGE_FLOATS], Bs[2 * STAGE_FLOATS];
    int g = blockIdx.z;
    int mBase = blockIdx.x * 128;
    float acc[2][8][4] = {};
    mma_gemm<8>(g_yz + (size_t)g * Mrows * 128, 128, g_opw + (size_t)g * 128 * 128,
                mBase, 0, acc, As, Bs);
    int lane = threadIdx.x & 31, wid = threadIdx.x >> 5;
    int gid = lane >> 2, tidx = lane & 3;
    int wm = (wid & 3) * 32, wn = (wid >> 2) * 64;
#pragma unroll
    for (int mt = 0; mt < 2; mt++)
#pragma unroll
    for (int half = 0; half < 2; half++) {
        int m = mBase + wm + mt * 16 + gid + half * 8;
        float* dst = g_ycat + (size_t)m * 512 + g * 128 + wn + 2 * tidx;
#pragma unroll
        for (int nt = 0; nt < 8; nt++) {
            float2 o = { acc[mt][nt][half * 2], acc[mt][nt][half * 2 + 1] };
            *(float2*)(dst + nt * 8) = o;
        }
    }
}

// ---------------- GEMM 3: final proj (transposed store + bias) -------------------
__global__ void __launch_bounds__(256) k_gemm_fin_mma(const float* __restrict__ pb,
                                                      float* __restrict__ out)
{
    __shared__ float As[2 * STAGE_FLOATS], Bs[2 * STAGE_FLOATS];
    int mBase = blockIdx.x * 128, nBase = blockIdx.y * 128;
    float acc[2][8][4] = {};
    mma_gemm<32>(g_xmn, 512, g_pw, mBase, nBase, acc, As, Bs);
    int lane = threadIdx.x & 31, wid = threadIdx.x >> 5;
    int gid = lane >> 2, tidx = lane & 3;
    int wm = (wid & 3) * 32, wn = (wid >> 2) * 64;
#pragma unroll
    for (int mt = 0; mt < 2; mt++)
#pragma unroll
    for (int half = 0; half < 2; half++) {
        int m = mBase + wm + mt * 16 + gid + half * 8;
        int b = m >> 12, l = m & 4095;
#pragma unroll
        for (int nt = 0; nt < 8; nt++) {
            int n = nBase + wn + nt * 8 + 2 * tidx;
            out[((size_t)(b * 512 + n)) * 4096 + l]     = acc[mt][nt][half * 2]     + __ldg(pb + n);
            out[((size_t)(b * 512 + n + 1)) * 4096 + l] = acc[mt][nt][half * 2 + 1] + __ldg(pb + n + 1);
        }
    }
}

// ---------------- kernel 5: depthwise conv + silu + cross_scan -----------------
__global__ void __launch_bounds__(256) k_conv(const float* __restrict__ cw,
                                              const float* __restrict__ cb)
{
    __shared__ float sx[324 * 32];
    __shared__ float wsm[32 * 9];
    __shared__ float bsm[32];
    int tile = blockIdx.x, dt = blockIdx.y, gb = blockIdx.z;
    int g = gb >> 3, b = gb & 7;
    int h0 = (tile >> 2) * 16, w0 = (tile & 3) * 16;
    int dbase = dt * 32;
    int tid = threadIdx.x;
    const float* src = g_xz + ((size_t)g * Mrows + b * Ls) * 256;
    for (int idx = tid; idx < 324 * 32; idx += 256) {
        int pos = idx >> 5, dd = idx & 31;
        int h = h0 + pos / 18 - 1, w = w0 + pos % 18 - 1;
        float v = 0.f;
        if (h >= 0 && h < 64 && w >= 0 && w < 64)
            v = src[(size_t)(h * 64 + w) * 256 + dbase + dd];
        sx[idx] = v;
    }
    for (int i = tid; i < 288; i += 256)
        wsm[i] = cw[(size_t)(g * 128 + dbase + i / 9) * 9 + i % 9];
    if (tid < 32)  bsm[tid] = cb[g * 128 + dbase + tid];
    __syncthreads();
    int dd = tid & 31;
    float* dstbase = g_u + ((size_t)g * Mrows + b * Ls) * 128 + dbase + dd;
#pragma unroll 4
    for (int it = 0; it < 32; it++) {
        int pos = it * 8 + (tid >> 5);
        int ph = pos >> 4, pw = pos & 15;
        float acc = bsm[dd];
#pragma unroll
        for (int kh = 0; kh < 3; kh++)
#pragma unroll
            for (int kw = 0; kw < 3; kw++)
                acc += sx[((ph + kh) * 18 + pw + kw) * 32 + dd] * wsm[dd * 9 + kh * 3 + kw];
        acc = acc / (1.f + expf(-acc));
        int h = h0 + ph, w = w0 + pw;
        int lp;
        if (g == 0)      lp = h * 64 + w;
        else if (g == 1) lp = w * 64 + h;
        else if (g == 2) lp = 4095 - (h * 64 + w);
        else             lp = 4095 - (w * 64 + h);
        dstbase[(size_t)lp * 128] = acc;
    }
}

// ---------------- kernel 6: x_proj + dt_proj + dA/dBu/C ------------------------
__global__ void __launch_bounds__(256) k_proj(const float* __restrict__ xpw,
                                              const float* __restrict__ dtw_g,
                                              const float* __restrict__ dtb_g,
                                              const float* __restrict__ alog)
{
    __shared__ float xp[10 * 128];
    __shared__ float dtwT[8 * 128];
    __shared__ float dtb[128];
    __shared__ float An[128];
    int tid = threadIdx.x, lane = tid & 31, warp = tid >> 5;
    int chunk0 = blockIdx.x * 8;
    int g = chunk0 >> 12;
    for (int i = tid; i < 1280; i += 256) xp[i] = xpw[(size_t)g * 1280 + i];
    for (int i = tid; i < 1024; i += 256) {
        int r = i >> 7, d = i & 127;
        dtwT[i] = dtw_g[(size_t)(g * 128 + d) * 8 + r];
    }
    if (tid < 128) { dtb[tid] = dtb_g[g * 128 + tid]; An[tid] = -expf(alog[g * 128 + tid]); }
    __syncthreads();
    int chunk = chunk0 + warp;
    int b = (chunk >> 9) & 7;
    int lp0 = (chunk & 511) * 8;
    size_t rowbase = (size_t)(g * 8 + b) * 4096 + lp0;
    for (int it = 0; it < 8; it++) {
        size_t row = rowbase + it;
        float4 u4 = *(const float4*)(g_u + row * 128 + lane * 4);
        float xdbl[10];
#pragma unroll
        for (int c = 0; c < 10; c++) {
            const float* xc = xp + c * 128 + lane * 4;
            float p = u4.x * xc[0] + u4.y * xc[1] + u4.z * xc[2] + u4.w * xc[3];
#pragma unroll
            for (int o = 16; o; o >>= 1) p += __shfl_xor_sync(0xffffffffu, p, o);
            xdbl[c] = p;
        }
        float Bm = xdbl[8];
        float uarr[4] = { u4.x, u4.y, u4.z, u4.w };
        float dA4[4], db4[4];
#pragma unroll
        for (int j = 0; j < 4; j++) {
            int d = lane * 4 + j;
            float s = dtb[d];
#pragma unroll
            for (int r = 0; r < 8; r++) s += xdbl[r] * dtwT[r * 128 + d];
            float delta = (s > 20.f) ? s : log1pf(expf(s));
            dA4[j] = expf(delta * An[d]);
            db4[j] = delta * uarr[j] * Bm;
        }
        *(float4*)(g_dA  + row * 128 + lane * 4) = *(float4*)dA4;
        *(float4*)(g_dbu + row * 128 + lane * 4) = *(float4*)db4;
        if (lane == 0) g_Cv[row] = xdbl[9];
    }
}

// ---------------- kernels 7-9: chunked parallel linear scan --------------------
__global__ void k_scanA()
{
    int chunk = blockIdx.x, gb = blockIdx.y, d = threadIdx.x;
    size_t base = ((size_t)gb * 4096 + chunk * 64) * 128 + d;
    float h = 0.f, P = 1.f;
#pragma unroll 4
    for (int i = 0; i < 64; i++) {
        float a = g_dA[base + (size_t)i * 128], bu = g_dbu[base + (size_t)i * 128];
        h = fmaf(a, h, bu); P *= a;
    }
    size_t o = ((size_t)gb * 64 + chunk) * 128 + d;
    g_P[o] = P; g_hc[o] = h;
}

__global__ void k_scanB()
{
    int gb = blockIdx.x, d = threadIdx.x;
    float h = 0.f;
    for (int ch = 0; ch < 64; ch++) {
        size_t o = ((size_t)gb * 64 + ch) * 128 + d;
        g_hin[o] = h;
        h = fmaf(g_P[o], h, g_hc[o]);
    }
}

__global__ void k_scanC(const float* __restrict__ Dsp)
{
    int chunk = blockIdx.x, gb = blockIdx.y, d = threadIdx.x;
    int g = gb >> 3;
    float Ds = Dsp[g * 128 + d];
    size_t base = ((size_t)gb * 4096 + chunk * 64) * 128 + d;
    size_t crow = (size_t)gb * 4096 + chunk * 64;
    float h = g_hin[((size_t)gb * 64 + chunk) * 128 + d];
#pragma unroll 4
    for (int i = 0; i < 64; i++) {
        size_t idx = base + (size_t)i * 128;
        h = fmaf(g_dA[idx], h, g_dbu[idx]);
        g_y[idx] = h * g_Cv[crow + i] + Ds * g_u[idx];
    }
}

// ---------------- kernel 10: cross_merge + LN(D) + *z ---------------------------
__global__ void __launch_bounds__(256) k_merge(const float* __restrict__ og_,
                                               const float* __restrict__ ob_)
{
    __shared__ float og[128], ob[128];
    int tid = threadIdx.x, lane = tid & 31, warp = tid >> 5;
    int chunk0 = blockIdx.x * 8;
    int g = chunk0 >> 12;
    if (tid < 128) { og[tid] = og_[g * 128 + tid]; ob[tid] = ob_[g * 128 + tid]; }
    __syncthreads();
    int chunk = chunk0 + warp;
    int b = (chunk >> 9) & 7;
    int l0 = (chunk & 511) * 8;
    for (int it = 0; it < 8; it++) {
        int l = l0 + it;
        int h = l >> 6, w = l & 63;
        int lp;
        if (g == 0)      lp = l;
        else if (g == 1) lp = w * 64 + h;
        else if (g == 2) lp = 4095 - l;
        else             lp = 4095 - (w * 64 + h);
        size_t srow = (size_t)(g * 8 + b) * 4096 + lp;
        float4 y4 = *(const float4*)(g_y + srow * 128 + lane * 4);
        float s  = y4.x + y4.y + y4.z + y4.w;
        float s2 = y4.x * y4.x + y4.y * y4.y + y4.z * y4.z + y4.w * y4.w;
#pragma unroll
        for (int o = 16; o; o >>= 1) {
            s  += __shfl_xor_sync(0xffffffffu, s, o);
            s2 += __shfl_xor_sync(0xffffffffu, s2, o);
        }
        float mu = s * (1.f / 128.f);
        float rs = rsqrtf(s2 * (1.f / 128.f) - mu * mu + 1e-5f);
        size_t drow = (size_t)(g * 8 + b) * 4096 + l;
        float4 z4 = *(const float4*)(g_xz + drow * 256 + 128 + lane * 4);
        float yv[4] = { y4.x, y4.y, y4.z, y4.w };
        float zv[4] = { z4.x, z4.y, z4.z, z4.w };
        float outv[4];
#pragma unroll
        for (int j = 0; j < 4; j++) {
            int d = lane * 4 + j;
            outv[j] = tf32r(((yv[j] - mu) * rs * og[d] + ob[d]) * zv[j]);
        }
        *(float4*)(g_yz + drow * 128 + lane * 4) = *(float4*)outv;
    }
}

// ---------------- kernel 12: mix + gate + LN(C) ---------------------------------
__global__ void __launch_bounds__(128) k_premix(const float* __restrict__ lg,
                                                const float* __restrict__ lb,
                                                const float* __restrict__ skip)
{
    int row = blockIdx.x, b = row >> 12, tid = threadIdx.x;
    float sk = skip[0];
    float4 yc = *(const float4*)(g_ycat + (size_t)row * 512 + tid * 4);
    float4 xn = *(const float4*)(g_xn   + (size_t)row * 512 + tid * 4);
    float4 gt = *(const float4*)(g_gate + (size_t)b   * 512 + tid * 4);
    float v[4] = { yc.x * sk * xn.x * gt.x, yc.y * sk * xn.y * gt.y,
                   yc.z * sk * xn.z * gt.z, yc.w * sk * xn.w * gt.w };
    float s  = v[0] + v[1] + v[2] + v[3];
    float s2 = v[0] * v[0] + v[1] * v[1] + v[2] * v[2] + v[3] * v[3];
#pragma unroll
    for (int o = 16; o; o >>= 1) {
        s  += __shfl_xor_sync(0xffffffffu, s, o);
        s2 += __shfl_xor_sync(0xffffffffu, s2, o);
    }
    __shared__ float rs_[4], rq_[4];
    int warp = tid >> 5, lane = tid & 31;
    if (lane == 0) { rs_[warp] = s; rq_[warp] = s2; }
    __syncthreads();
    s  = rs_[0] + rs_[1] + rs_[2] + rs_[3];
    s2 = rq_[0] + rq_[1] + rq_[2] + rq_[3];
    float mu = s * (1.f / 512.f);
    float rstd = rsqrtf(s2 * (1.f / 512.f) - mu * mu + 1e-5f);
    float o4[4];
#pragma unroll
    for (int j = 0; j < 4; j++) {
        int c = tid * 4 + j;
        o4[j] = tf32r((v[j] - mu) * rstd * lg[c] + lb[c]);
    }
    *(float4*)(g_xmn + (size_t)row * 512 + tid * 4) = *(float4*)o4;
}

// ---------------- launch ---------------------------------------------------------
extern "C" void kernel_launch(void* const* d_in, const int* in_sizes, int n_in,
                              void* d_out, int out_size)
{
    const float* x    = (const float*)d_in[0];
    const float* ln_g = (const float*)d_in[1];
    const float* ln_b = (const float*)d_in[2];
    const float* fc1w = (const float*)d_in[3];
    const float* fc1b = (const float*)d_in[4];
    const float* fc2w = (const float*)d_in[5];
    const float* fc2b = (const float*)d_in[6];
    const float* ipw  = (const float*)d_in[7];
    const float* cw   = (const float*)d_in[8];
    const float* cb   = (const float*)d_in[9];
    const float* xpw  = (const float*)d_in[10];
    const float* dtw  = (const float*)d_in[11];
    const float* dtb  = (const float*)d_in[12];
    const float* alog = (const float*)d_in[13];
    const float* dsp  = (const float*)d_in[14];
    const float* ong  = (const float*)d_in[15];
    const float* onb  = (const float*)d_in[16];
    const float* opw  = (const float*)d_in[17];
    const float* pw   = (const float*)d_in[18];
    const float* pb   = (const float*)d_in[19];
    const float* skip = (const float*)d_in[20];
    float* out = (float*)d_out;

    k_ln1         <<<dim3(32, 8),     128>>>(x, ln_g, ln_b);
    k_roundw      <<<1024,            256>>>(ipw, opw, pw);
    k_zsum        <<<dim3(32, 8),     512>>>();
    k_gate        <<<1,               256>>>(fc1w, fc1b, fc2w, fc2b);
    k_gemm_in_mma <<<dim3(256, 2, 4), 256>>>();
    k_conv        <<<dim3(16, 4, 32), 256>>>(cw, cb);
    k_proj        <<<2048,            256>>>(xpw, dtw, dtb, alog);
    k_scanA       <<<dim3(64, 32),    128>>>();
    k_scanB       <<<32,              128>>>();
    k_scanC       <<<dim3(64, 32),    128>>>(dsp);
    k_merge       <<<2048,            256>>>(ong, onb);
    k_gemm_out_mma<<<dim3(256, 1, 4), 256>>>();
    k_premix      <<<32768,           128>>>(ln_g, ln_b, skip);
    k_gemm_fin_mma<<<dim3(256, 4),    256>>>(pb, out);
}

// round 12
// speedup vs baseline: 1.8818x; 1.1847x over previous
#include <cuda_runtime.h>
#include <math.h>
#include <stdint.h>

// Problem constants
#define Bsz 8
#define Cch 512
#define Ls 4096
#define Gg 4
#define Dd 128
#define Mrows 32768   // B*L

// ---------------- scratch (device globals; no cudaMalloc allowed) -------------
__device__ float g_xn  [(size_t)Bsz*Ls*Cch];
__device__ float g_zp  [32*Bsz*Cch];
__device__ float g_gate[Bsz*Cch];
__device__ float g_xz  [(size_t)Gg*Mrows*256];
__device__ float g_u   [(size_t)Gg*Mrows*Dd];
__device__ float g_dA  [(size_t)Gg*Mrows*Dd];
__device__ float g_dbu [(size_t)Gg*Mrows*Dd];
__device__ float g_Cv  [Gg*Mrows];
__device__ float g_P   [Gg*Bsz*64*Dd];
__device__ float g_hc  [Gg*Bsz*64*Dd];
__device__ float g_hin [Gg*Bsz*64*Dd];
__device__ float g_y   [(size_t)Gg*Mrows*Dd];
__device__ float g_yz  [(size_t)Gg*Mrows*Dd];
__device__ float g_ycat[(size_t)Mrows*Cch];
__device__ float g_xmn [(size_t)Mrows*Cch];
// tf32-rounded weight copies
__device__ float g_ipw [Gg*256*128];
__device__ float g_opw [Gg*128*128];
__device__ float g_pw  [512*512];

// ---------------- helpers -------------------------------------------------------
__device__ __forceinline__ float tf32r(float x) {
    uint32_t u;
    asm("cvt.rna.tf32.f32 %0, %1;" : "=r"(u) : "f"(x));
    return __uint_as_float(u);
}
__device__ __forceinline__ uint32_t sm_u32(const void* p) {
    return (uint32_t)__cvta_generic_to_shared(p);
}
__device__ __forceinline__ void cpa16(uint32_t dst, const float* src) {
    asm volatile("cp.async.cg.shared.global [%0], [%1], 16;" :: "r"(dst), "l"(src));
}
__device__ __forceinline__ void cpa_commit() { asm volatile("cp.async.commit_group;"); }
template<int N> __device__ __forceinline__ void cpa_wait() {
    asm volatile("cp.async.wait_group %0;" :: "n"(N));
}
__device__ __forceinline__ void mma_tf32_16n8k8(float* c, const uint32_t* a, const uint32_t* b) {
    asm volatile(
        "mma.sync.aligned.m16n8k8.row.col.f32.tf32.tf32.f32 "
        "{%0,%1,%2,%3}, {%4,%5,%6,%7}, {%8,%9}, {%0,%1,%2,%3};"
        : "+f"(c[0]), "+f"(c[1]), "+f"(c[2]), "+f"(c[3])
        : "r"(a[0]), "r"(a[1]), "r"(a[2]), "r"(a[3]), "r"(b[0]), "r"(b[1]));
}

// SMEM stage: 128 rows x 16 cols, row pitch 20 floats (conflict-free fragments)
#define SPITCH 20
#define STAGE_FLOATS (128 * SPITCH)

__device__ __forceinline__ void stage_load(const float* __restrict__ g, int ld,
                                           int r0, int k0, float* sbuf, int tid)
{
#pragma unroll
    for (int i = 0; i < 2; i++) {
        int s = tid + (i << 8);          // 0..511
        int r = s >> 2, seg = s & 3;
        cpa16(sm_u32(sbuf + r * SPITCH + seg * 4),
              g + (size_t)(r0 + r) * ld + k0 + seg * 4);
    }
}

// ---------------- tf32 mma.sync 128x128xK core ----------------------------------
template<int S>   // S = K/16 stages
__device__ __forceinline__ void mma_gemm(const float* __restrict__ Ag, int lda,
                                         const float* __restrict__ Bg,
                                         int mBase, int nBase,
                                         float acc[2][8][4],
                                         float* As, float* Bs)
{
    const int KTOT = 16 * S;
    int tid = threadIdx.x, wid = tid >> 5, lane = tid & 31;
    int gid = lane >> 2, tidx = lane & 3;
    int wm = (wid & 3) * 32, wn = (wid >> 2) * 64;

    stage_load(Ag, lda, mBase, 0, As, tid);
    stage_load(Bg, KTOT, nBase, 0, Bs, tid);
    cpa_commit();

    for (int s = 0; s < S; s++) {
        if (s + 1 < S) {
            int nb = (s + 1) & 1;
            stage_load(Ag, lda, mBase, (s + 1) * 16, As + nb * STAGE_FLOATS, tid);
            stage_load(Bg, KTOT, nBase, (s + 1) * 16, Bs + nb * STAGE_FLOATS, tid);
            cpa_commit();
            cpa_wait<1>();
        } else {
            cpa_wait<0>();
        }
        __syncthreads();
        const float* Ab = As + (s & 1) * STAGE_FLOATS;
        const float* Bb = Bs + (s & 1) * STAGE_FLOATS;
#pragma unroll
        for (int kk = 0; kk < 16; kk += 8) {
            uint32_t afr[2][4];
#pragma unroll
            for (int mt = 0; mt < 2; mt++) {
                const float* ap = Ab + (wm + mt * 16 + gid) * SPITCH + kk + tidx;
                afr[mt][0] = __float_as_uint(ap[0]);
                afr[mt][1] = __float_as_uint(ap[8 * SPITCH]);
                afr[mt][2] = __float_as_uint(ap[4]);
                afr[mt][3] = __float_as_uint(ap[8 * SPITCH + 4]);
            }
            uint32_t bfr[8][2];
#pragma unroll
            for (int nt = 0; nt < 8; nt++) {
                const float* bp = Bb + (wn + nt * 8 + gid) * SPITCH + kk + tidx;
                bfr[nt][0] = __float_as_uint(bp[0]);
                bfr[nt][1] = __float_as_uint(bp[4]);
            }
#pragma unroll
            for (int mt = 0; mt < 2; mt++)
#pragma unroll
                for (int nt = 0; nt < 8; nt++)
                    mma_tf32_16n8k8(acc[mt][nt], afr[mt], bfr[nt]);
        }
        __syncthreads();
    }
}

// ---------------- kernel 1: layernorm over C ----------------------------------
__global__ void k_ln1(const float* __restrict__ x,
                      const float* __restrict__ lg, const float* __restrict__ lb)
{
    int b = blockIdx.y;
    int l = blockIdx.x * 128 + threadIdx.x;
    const float* xp = x + (size_t)b * Cch * Ls + l;
    float s = 0.f, s2 = 0.f;
#pragma unroll 8
    for (int c = 0; c < Cch; c++) { float v = xp[(size_t)c * Ls]; s += v; s2 += v * v; }
    float mu = s * (1.f / Cch);
    float rs = rsqrtf(s2 * (1.f / Cch) - mu * mu + 1e-5f);
    float* out = g_xn + ((size_t)b * Ls + l) * Cch;
#pragma unroll 4
    for (int c = 0; c < Cch; c += 4) {
        float4 o;
        o.x = tf32r((xp[(size_t)(c + 0) * Ls] - mu) * rs * lg[c + 0] + lb[c + 0]);
        o.y = tf32r((xp[(size_t)(c + 1) * Ls] - mu) * rs * lg[c + 1] + lb[c + 1]);
        o.z = tf32r((xp[(size_t)(c + 2) * Ls] - mu) * rs * lg[c + 2] + lb[c + 2]);
        o.w = tf32r((xp[(size_t)(c + 3) * Ls] - mu) * rs * lg[c + 3] + lb[c + 3]);
        *(float4*)(out + c) = o;
    }
}

// ---------------- kernel 2: partial column sums -------------------------------
__global__ void k_zsum()
{
    int b = blockIdx.y, k = blockIdx.x, c = threadIdx.x;
    const float* p = g_xn + ((size_t)b * Ls + k * 128) * Cch + c;
    float s = 0.f;
#pragma unroll 8
    for (int i = 0; i < 128; i++) s += p[(size_t)i * Cch];
    g_zp[(k * Bsz + b) * Cch + c] = s;
}

// ---------------- kernel 3: gate MLP — parallel (one block per batch) ----------
__global__ void __launch_bounds__(256) k_gate(const float* __restrict__ fc1w,
                                              const float* __restrict__ fc1b,
                                              const float* __restrict__ fc2w,
                                              const float* __restrict__ fc2b)
{
    __shared__ float zsm[512];
    __shared__ float hsm[32];
    int t = threadIdx.x, b = blockIdx.x;
    int warp = t >> 5, lane = t & 31;
    for (int c = t; c < 512; c += 256) {
        float s = 0.f;
#pragma unroll
        for (int k = 0; k < 32; k++) s += g_zp[(k * Bsz + b) * 512 + c];
        zsm[c] = s * (1.f / Ls);
    }
    __syncthreads();
    for (int r = warp; r < 32; r += 8) {
        float p = 0.f;
#pragma unroll 4
        for (int i = lane; i < 512; i += 32) p += zsm[i] * fc1w[r * 512 + i];
#pragma unroll
        for (int o = 16; o; o >>= 1) p += __shfl_xor_sync(0xffffffffu, p, o);
        if (lane == 0) hsm[r] = fmaxf(p + fc1b[r], 0.f);
    }
    __syncthreads();
    for (int c = t; c < 512; c += 256) {
        float s = fc2b[c];
#pragma unroll
        for (int r = 0; r < 32; r++) s += hsm[r] * fc2w[c * 32 + r];
        g_gate[b * 512 + c] = 1.f / (1.f + expf(-s));
    }
}

// ---------------- weight rounding (tf32 RNE) ------------------------------------
__global__ void k_roundw(const float* __restrict__ ipw, const float* __restrict__ opw,
                         const float* __restrict__ pw)
{
    int i = blockIdx.x * 256 + threadIdx.x;
    if (i < Gg * 256 * 128) g_ipw[i] = tf32r(ipw[i]);
    if (i < Gg * 128 * 128) g_opw[i] = tf32r(opw[i]);
    if (i < 512 * 512)      g_pw[i]  = tf32r(pw[i]);
}

// ---------------- GEMM 1: in_proj (fused SiLU on z half) ------------------------
__global__ void __launch_bounds__(256) k_gemm_in_mma()
{
    __shared__ float As[2 * STAGE_FLOATS], Bs[2 * STAGE_FLOATS];
    int g = blockIdx.z;
    int mBase = blockIdx.x * 128, nBase = blockIdx.y * 128;
    float acc[2][8][4] = {};
    mma_gemm<8>(g_xn + g * 128, Cch, g_ipw + (size_t)g * 256 * 128,
                mBase, nBase, acc, As, Bs);
    int lane = threadIdx.x & 31, wid = threadIdx.x >> 5;
    int gid = lane >> 2, tidx = lane & 3;
    int wm = (wid & 3) * 32, wn = (wid >> 2) * 64;
    bool dosilu = (nBase >= 128);
    float* Cp = g_xz + (size_t)g * Mrows * 256;
#pragma unroll
    for (int mt = 0; mt < 2; mt++)
#pragma unroll
    for (int half = 0; half < 2; half++) {
        int m = mBase + wm + mt * 16 + gid + half * 8;
        float* dst = Cp + (size_t)m * 256 + nBase + wn + 2 * tidx;
#pragma unroll
        for (int nt = 0; nt < 8; nt++) {
            float v0 = acc[mt][nt][half * 2], v1 = acc[mt][nt][half * 2 + 1];
            if (dosilu) { v0 = v0 / (1.f + expf(-v0)); v1 = v1 / (1.f + expf(-v1)); }
            float2 o = { v0, v1 };
            *(float2*)(dst + nt * 8) = o;
        }
    }
}

// ---------------- GEMM 2: out_proj ----------------------------------------------
__global__ void __launch_bounds__(256) k_gemm_out_mma()
{
    __shared__ float As[2 * STAGE_FLOATS], Bs[2 * STAGE_FLOATS];
    int g = blockIdx.z;
    int mBase = blockIdx.x * 128;
    float acc[2][8][4] = {};
    mma_gemm<8>(g_yz + (size_t)g * Mrows * 128, 128, g_opw + (size_t)g * 128 * 128,
                mBase, 0, acc, As, Bs);
    int lane = threadIdx.x & 31, wid = threadIdx.x >> 5;
    int gid = lane >> 2, tidx = lane & 3;
    int wm = (wid & 3) * 32, wn = (wid >> 2) * 64;
#pragma unroll
    for (int mt = 0; mt < 2; mt++)
#pragma unroll
    for (int half = 0; half < 2; half++) {
        int m = mBase + wm + mt * 16 + gid + half * 8;
        float* dst = g_ycat + (size_t)m * 512 + g * 128 + wn + 2 * tidx;
#pragma unroll
        for (int nt = 0; nt < 8; nt++) {
            float2 o = { acc[mt][nt][half * 2], acc[mt][nt][half * 2 + 1] };
            *(float2*)(dst + nt * 8) = o;
        }
    }
}

// ---------------- GEMM 3: final proj (transposed store + bias) -------------------
__global__ void __launch_bounds__(256) k_gemm_fin_mma(const float* __restrict__ pb,
                                                      float* __restrict__ out)
{
    __shared__ float As[2 * STAGE_FLOATS], Bs[2 * STAGE_FLOATS];
    int mBase = blockIdx.x * 128, nBase = blockIdx.y * 128;
    float acc[2][8][4] = {};
    mma_gemm<32>(g_xmn, 512, g_pw, mBase, nBase, acc, As, Bs);
    int lane = threadIdx.x & 31, wid = threadIdx.x >> 5;
    int gid = lane >> 2, tidx = lane & 3;
    int wm = (wid & 3) * 32, wn = (wid >> 2) * 64;
#pragma unroll
    for (int mt = 0; mt < 2; mt++)
#pragma unroll
    for (int half = 0; half < 2; half++) {
        int m = mBase + wm + mt * 16 + gid + half * 8;
        int b = m >> 12, l = m & 4095;
#pragma unroll
        for (int nt = 0; nt < 8; nt++) {
            int n = nBase + wn + nt * 8 + 2 * tidx;
            out[((size_t)(b * 512 + n)) * 4096 + l]     = acc[mt][nt][half * 2]     + __ldg(pb + n);
            out[((size_t)(b * 512 + n + 1)) * 4096 + l] = acc[mt][nt][half * 2 + 1] + __ldg(pb + n + 1);
        }
    }
}

// ---------------- kernel 5: depthwise conv + silu + cross_scan -----------------
__global__ void __launch_bounds__(256) k_conv(const float* __restrict__ cw,
                                              const float* __restrict__ cb)
{
    __shared__ float sx[324 * 32];
    __shared__ float wsm[32 * 9];
    __shared__ float bsm[32];
    int tile = blockIdx.x, dt = blockIdx.y, gb = blockIdx.z;
    int g = gb >> 3, b = gb & 7;
    int h0 = (tile >> 2) * 16, w0 = (tile & 3) * 16;
    int dbase = dt * 32;
    int tid = threadIdx.x;
    const float* src = g_xz + ((size_t)g * Mrows + b * Ls) * 256;
    for (int idx = tid; idx < 324 * 32; idx += 256) {
        int pos = idx >> 5, dd = idx & 31;
        int h = h0 + pos / 18 - 1, w = w0 + pos % 18 - 1;
        float v = 0.f;
        if (h >= 0 && h < 64 && w >= 0 && w < 64)
            v = src[(size_t)(h * 64 + w) * 256 + dbase + dd];
        sx[idx] = v;
    }
    for (int i = tid; i < 288; i += 256)
        wsm[i] = cw[(size_t)(g * 128 + dbase + i / 9) * 9 + i % 9];
    if (tid < 32)  bsm[tid] = cb[g * 128 + dbase + tid];
    __syncthreads();
    int dd = tid & 31;
    float* dstbase = g_u + ((size_t)g * Mrows + b * Ls) * 128 + dbase + dd;
#pragma unroll 4
    for (int it = 0; it < 32; it++) {
        int pos = it * 8 + (tid >> 5);
        int ph = pos >> 4, pw = pos & 15;
        float acc = bsm[dd];
#pragma unroll
        for (int kh = 0; kh < 3; kh++)
#pragma unroll
            for (int kw = 0; kw < 3; kw++)
                acc += sx[((ph + kh) * 18 + pw + kw) * 32 + dd] * wsm[dd * 9 + kh * 3 + kw];
        acc = acc / (1.f + expf(-acc));
        int h = h0 + ph, w = w0 + pw;
        int lp;
        if (g == 0)      lp = h * 64 + w;
        else if (g == 1) lp = w * 64 + h;
        else if (g == 2) lp = 4095 - (h * 64 + w);
        else             lp = 4095 - (w * 64 + h);
        dstbase[(size_t)lp * 128] = acc;
    }
}

// ---------------- kernel 6: x_proj + dt_proj + dA/dBu/C ------------------------
__global__ void __launch_bounds__(256) k_proj(const float* __restrict__ xpw,
                                              const float* __restrict__ dtw_g,
                                              const float* __restrict__ dtb_g,
                                              const float* __restrict__ alog)
{
    __shared__ float xp[10 * 128];
    __shared__ float dtwT[8 * 128];
    __shared__ float dtb[128];
    __shared__ float An[128];
    int tid = threadIdx.x, lane = tid & 31, warp = tid >> 5;
    int chunk0 = blockIdx.x * 8;
    int g = chunk0 >> 12;
    for (int i = tid; i < 1280; i += 256) xp[i] = xpw[(size_t)g * 1280 + i];
    for (int i = tid; i < 1024; i += 256) {
        int r = i >> 7, d = i & 127;
        dtwT[i] = dtw_g[(size_t)(g * 128 + d) * 8 + r];
    }
    if (tid < 128) { dtb[tid] = dtb_g[g * 128 + tid]; An[tid] = -expf(alog[g * 128 + tid]); }
    __syncthreads();
    int chunk = chunk0 + warp;
    int b = (chunk >> 9) & 7;
    int lp0 = (chunk & 511) * 8;
    size_t rowbase = (size_t)(g * 8 + b) * 4096 + lp0;
    for (int it = 0; it < 8; it++) {
        size_t row = rowbase + it;
        float4 u4 = *(const float4*)(g_u + row * 128 + lane * 4);
        float xdbl[10];
#pragma unroll
        for (int c = 0; c < 10; c++) {
            const float* xc = xp + c * 128 + lane * 4;
            float p = u4.x * xc[0] + u4.y * xc[1] + u4.z * xc[2] + u4.w * xc[3];
#pragma unroll
            for (int o = 16; o; o >>= 1) p += __shfl_xor_sync(0xffffffffu, p, o);
            xdbl[c] = p;
        }
        float Bm = xdbl[8];
        float uarr[4] = { u4.x, u4.y, u4.z, u4.w };
        float dA4[4], db4[4];
#pragma unroll
        for (int j = 0; j < 4; j++) {
            int d = lane * 4 + j;
            float s = dtb[d];
#pragma unroll
            for (int r = 0; r < 8; r++) s += xdbl[r] * dtwT[r * 128 + d];
            float delta = (s > 20.f) ? s : log1pf(expf(s));
            dA4[j] = expf(delta * An[d]);
            db4[j] = delta * uarr[j] * Bm;
        }
        *(float4*)(g_dA  + row * 128 + lane * 4) = *(float4*)dA4;
        *(float4*)(g_dbu + row * 128 + lane * 4) = *(float4*)db4;
        if (lane == 0) g_Cv[row] = xdbl[9];
    }
}

// ---------------- kernels 7-9: chunked parallel linear scan --------------------
__global__ void k_scanA()
{
    int chunk = blockIdx.x, gb = blockIdx.y, d = threadIdx.x;
    size_t base = ((size_t)gb * 4096 + chunk * 64) * 128 + d;
    float h = 0.f, P = 1.f;
#pragma unroll 4
    for (int i = 0; i < 64; i++) {
        float a = g_dA[base + (size_t)i * 128], bu = g_dbu[base + (size_t)i * 128];
        h = fmaf(a, h, bu); P *= a;
    }
    size_t o = ((size_t)gb * 64 + chunk) * 128 + d;
    g_P[o] = P; g_hc[o] = h;
}

__global__ void k_scanB()
{
    int gb = blockIdx.x, d = threadIdx.x;
    float h = 0.f;
    for (int ch = 0; ch < 64; ch++) {
        size_t o = ((size_t)gb * 64 + ch) * 128 + d;
        g_hin[o] = h;
        h = fmaf(g_P[o], h, g_hc[o]);
    }
}

__global__ void k_scanC(const float* __restrict__ Dsp)
{
    int chunk = blockIdx.x, gb = blockIdx.y, d = threadIdx.x;
    int g = gb >> 3;
    float Ds = Dsp[g * 128 + d];
    size_t base = ((size_t)gb * 4096 + chunk * 64) * 128 + d;
    size_t crow = (size_t)gb * 4096 + chunk * 64;
    float h = g_hin[((size_t)gb * 64 + chunk) * 128 + d];
#pragma unroll 4
    for (int i = 0; i < 64; i++) {
        size_t idx = base + (size_t)i * 128;
        h = fmaf(g_dA[idx], h, g_dbu[idx]);
        g_y[idx] = h * g_Cv[crow + i] + Ds * g_u[idx];
    }
}

// ---------------- kernel 10: cross_merge + LN(D) + *z ---------------------------
__global__ void __launch_bounds__(256) k_merge(const float* __restrict__ og_,
                                               const float* __restrict__ ob_)
{
    __shared__ float og[128], ob[128];
    int tid = threadIdx.x, lane = tid & 31, warp = tid >> 5;
    int chunk0 = blockIdx.x * 8;
    int g = chunk0 >> 12;
    if (tid < 128) { og[tid] = og_[g * 128 + tid]; ob[tid] = ob_[g * 128 + tid]; }
    __syncthreads();
    int chunk = chunk0 + warp;
    int b = (chunk >> 9) & 7;
    int l0 = (chunk & 511) * 8;
    for (int it = 0; it < 8; it++) {
        int l = l0 + it;
        int h = l >> 6, w = l & 63;
        int lp;
        if (g == 0)      lp = l;
        else if (g == 1) lp = w * 64 + h;
        else if (g == 2) lp = 4095 - l;
        else             lp = 4095 - (w * 64 + h);
        size_t srow = (size_t)(g * 8 + b) * 4096 + lp;
        float4 y4 = *(const float4*)(g_y + srow * 128 + lane * 4);
        float s  = y4.x + y4.y + y4.z + y4.w;
        float s2 = y4.x * y4.x + y4.y * y4.y + y4.z * y4.z + y4.w * y4.w;
#pragma unroll
        for (int o = 16; o; o >>= 1) {
            s  += __shfl_xor_sync(0xffffffffu, s, o);
            s2 += __shfl_xor_sync(0xffffffffu, s2, o);
        }
        float mu = s * (1.f / 128.f);
        float rs = rsqrtf(s2 * (1.f / 128.f) - mu * mu + 1e-5f);
        size_t drow = (size_t)(g * 8 + b) * 4096 + l;
        float4 z4 = *(const float4*)(g_xz + drow * 256 + 128 + lane * 4);
        float yv[4] = { y4.x, y4.y, y4.z, y4.w };
        float zv[4] = { z4.x, z4.y, z4.z, z4.w };
        float outv[4];
#pragma unroll
        for (int j = 0; j < 4; j++) {
            int d = lane * 4 + j;
            outv[j] = tf32r(((yv[j] - mu) * rs * og[d] + ob[d]) * zv[j]);
        }
        *(float4*)(g_yz + drow * 128 + lane * 4) = *(float4*)outv;
    }
}

// ---------------- kernel 12: mix + gate + LN(C) ---------------------------------
__global__ void __launch_bounds__(128) k_premix(const float* __restrict__ lg,
                                                const float* __restrict__ lb,
                                                const float* __restrict__ skip)
{
    int row = blockIdx.x, b = row >> 12, tid = threadIdx.x;
    float sk = skip[0];
    float4 yc = *(const float4*)(g_ycat + (size_t)row * 512 + tid * 4);
    float4 xn = *(const float4*)(g_xn   + (size_t)row * 512 + tid * 4);
    float4 gt = *(const float4*)(g_gate + (size_t)b   * 512 + tid * 4);
    float v[4] = { yc.x * sk * xn.x * gt.x, yc.y * sk * xn.y * gt.y,
                   yc.z * sk * xn.z * gt.z, yc.w * sk * xn.w * gt.w };
    float s  = v[0] + v[1] + v[2] + v[3];
    float s2 = v[0] * v[0] + v[1] * v[1] + v[2] * v[2] + v[3] * v[3];
#pragma unroll
    for (int o = 16; o; o >>= 1) {
        s  += __shfl_xor_sync(0xffffffffu, s, o);
        s2 += __shfl_xor_sync(0xffffffffu, s2, o);
    }
    __shared__ float rs_[4], rq_[4];
    int warp = tid >> 5, lane = tid & 31;
    if (lane == 0) { rs_[warp] = s; rq_[warp] = s2; }
    __syncthreads();
    s  = rs_[0] + rs_[1] + rs_[2] + rs_[3];
    s2 = rq_[0] + rq_[1] + rq_[2] + rq_[3];
    float mu = s * (1.f / 512.f);
    float rstd = rsqrtf(s2 * (1.f / 512.f) - mu * mu + 1e-5f);
    float o4[4];
#pragma unroll
    for (int j = 0; j < 4; j++) {
        int c = tid * 4 + j;
        o4[j] = tf32r((v[j] - mu) * rstd * lg[c] + lb[c]);
    }
    *(float4*)(g_xmn + (size_t)row * 512 + tid * 4) = *(float4*)o4;
}

// ---------------- launch ---------------------------------------------------------
extern "C" void kernel_launch(void* const* d_in, const int* in_sizes, int n_in,
                              void* d_out, int out_size)
{
    const float* x    = (const float*)d_in[0];
    const float* ln_g = (const float*)d_in[1];
    const float* ln_b = (const float*)d_in[2];
    const float* fc1w = (const float*)d_in[3];
    const float* fc1b = (const float*)d_in[4];
    const float* fc2w = (const float*)d_in[5];
    const float* fc2b = (const float*)d_in[6];
    const float* ipw  = (const float*)d_in[7];
    const float* cw   = (const float*)d_in[8];
    const float* cb   = (const float*)d_in[9];
    const float* xpw  = (const float*)d_in[10];
    const float* dtw  = (const float*)d_in[11];
    const float* dtb  = (const float*)d_in[12];
    const float* alog = (const float*)d_in[13];
    const float* dsp  = (const float*)d_in[14];
    const float* ong  = (const float*)d_in[15];
    const float* onb  = (const float*)d_in[16];
    const float* opw  = (const float*)d_in[17];
    const float* pw   = (const float*)d_in[18];
    const float* pb   = (const float*)d_in[19];
    const float* skip = (const float*)d_in[20];
    float* out = (float*)d_out;

    k_ln1         <<<dim3(32, 8),     128>>>(x, ln_g, ln_b);
    k_roundw      <<<1024,            256>>>(ipw, opw, pw);
    k_zsum        <<<dim3(32, 8),     512>>>();
    k_gate        <<<8,               256>>>(fc1w, fc1b, fc2w, fc2b);
    k_gemm_in_mma <<<dim3(256, 2, 4), 256>>>();
    k_conv        <<<dim3(16, 4, 32), 256>>>(cw, cb);
    k_proj        <<<2048,            256>>>(xpw, dtw, dtb, alog);
    k_scanA       <<<dim3(64, 32),    128>>>();
    k_scanB       <<<32,              128>>>();
    k_scanC       <<<dim3(64, 32),    128>>>(dsp);
    k_merge       <<<2048,            256>>>(ong, onb);
    k_gemm_out_mma<<<dim3(256, 1, 4), 256>>>();
    k_premix      <<<32768,           128>>>(ln_g, ln_b, skip);
    k_gemm_fin_mma<<<dim3(256, 4),    256>>>(pb, out);
}